// round 2
// baseline (speedup 1.0000x reference)
#include <cuda_runtime.h>

#define BB 2
#define LL 2048
#define DD 1024
#define HH 16
#define DH 64
#define BM 64
#define BN 64

// scratch for attention output (merged heads), [B, L, D] fp32 = 16 MB
__device__ float g_attn[BB * LL * DD];

// ---------------------------------------------------------------------------
// Flash attention, fp32, one block per (q-tile, head, batch).
// 256 threads, 4x4 register micro-tile per thread.
// Smem: Qt[k][r] (Q transposed, pre-scaled), KP (union of Kt[k][c] and Pt[c][r]),
//       Vs[c][d].  48 KB total.
// ---------------------------------------------------------------------------
__global__ __launch_bounds__(256) void attn_kernel(
    const float* __restrict__ Q,
    const float* __restrict__ K,
    const float* __restrict__ V)
{
    __shared__ float Qt[DH][BM];   // 16 KB
    __shared__ float KP[BN][BM];   // 16 KB  (Kt during S, Pt during PV)
    __shared__ float Vs[BN][DH];   // 16 KB

    const int tid = threadIdx.x;
    const int qt  = blockIdx.x;   // 0..31
    const int h   = blockIdx.y;
    const int b   = blockIdx.z;
    const int q0  = qt * BM;

    const int tr = tid >> 4;      // 0..15 -> rows r0..r0+3
    const int tc = tid & 15;      // 0..15 -> cols c0..c0+3
    const int r0 = tr * 4;
    const int c0 = tc * 4;

    const size_t base = (size_t)b * LL * DD + (size_t)h * DH;

    // ---- load Q tile transposed, pre-scaled by 1/sqrt(64) ----
    {
        const int row = tid >> 2;            // 0..63 (query row in tile)
        const int ks  = (tid & 3) * 16;      // 0,16,32,48
        const float* src = Q + base + (size_t)(q0 + row) * DD + ks;
        #pragma unroll
        for (int j4 = 0; j4 < 4; ++j4) {
            float4 v = *(const float4*)(src + j4 * 4);
            Qt[ks + j4 * 4 + 0][row] = v.x * 0.125f;
            Qt[ks + j4 * 4 + 1][row] = v.y * 0.125f;
            Qt[ks + j4 * 4 + 2][row] = v.z * 0.125f;
            Qt[ks + j4 * 4 + 3][row] = v.w * 0.125f;
        }
    }

    float acc[4][4];
    #pragma unroll
    for (int i = 0; i < 4; ++i)
        #pragma unroll
        for (int j = 0; j < 4; ++j) acc[i][j] = 0.0f;

    float mrow[4]  = {-1e30f, -1e30f, -1e30f, -1e30f};
    float lpart[4] = {0.0f, 0.0f, 0.0f, 0.0f};

    for (int kv = 0; kv <= qt; ++kv) {
        const int k0 = kv * BN;

        __syncthreads();  // prev-iter readers of KP/Vs done; also orders Qt init

        // ---- load K tile transposed, V tile straight ----
        {
            const int row = tid >> 2;        // key index within tile
            const int ks  = (tid & 3) * 16;
            const float* ksrc = K + base + (size_t)(k0 + row) * DD + ks;
            #pragma unroll
            for (int j4 = 0; j4 < 4; ++j4) {
                float4 v = *(const float4*)(ksrc + j4 * 4);
                KP[ks + j4 * 4 + 0][row] = v.x;
                KP[ks + j4 * 4 + 1][row] = v.y;
                KP[ks + j4 * 4 + 2][row] = v.z;
                KP[ks + j4 * 4 + 3][row] = v.w;
            }
            const float* vsrc = V + base + (size_t)(k0 + row) * DD + ks;
            #pragma unroll
            for (int j4 = 0; j4 < 4; ++j4) {
                *(float4*)&Vs[row][ks + j4 * 4] = *(const float4*)(vsrc + j4 * 4);
            }
        }
        __syncthreads();

        // ---- S = (Q/8) K^T  (4x4 micro-tile) ----
        float s[4][4];
        #pragma unroll
        for (int i = 0; i < 4; ++i)
            #pragma unroll
            for (int j = 0; j < 4; ++j) s[i][j] = 0.0f;

        #pragma unroll 8
        for (int k = 0; k < DH; ++k) {
            float4 qa = *(const float4*)&Qt[k][r0];
            float4 kb = *(const float4*)&KP[k][c0];
            s[0][0] += qa.x * kb.x; s[0][1] += qa.x * kb.y; s[0][2] += qa.x * kb.z; s[0][3] += qa.x * kb.w;
            s[1][0] += qa.y * kb.x; s[1][1] += qa.y * kb.y; s[1][2] += qa.y * kb.z; s[1][3] += qa.y * kb.w;
            s[2][0] += qa.z * kb.x; s[2][1] += qa.z * kb.y; s[2][2] += qa.z * kb.z; s[2][3] += qa.z * kb.w;
            s[3][0] += qa.w * kb.x; s[3][1] += qa.w * kb.y; s[3][2] += qa.w * kb.z; s[3][3] += qa.w * kb.w;
        }

        // ---- causal mask on diagonal tile ----
        if (kv == qt) {
            #pragma unroll
            for (int i = 0; i < 4; ++i)
                #pragma unroll
                for (int j = 0; j < 4; ++j)
                    if (c0 + j > r0 + i) s[i][j] = -1e30f;
        }

        // ---- online softmax update ----
        float tm[4];
        #pragma unroll
        for (int i = 0; i < 4; ++i)
            tm[i] = fmaxf(fmaxf(s[i][0], s[i][1]), fmaxf(s[i][2], s[i][3]));
        #pragma unroll
        for (int off = 1; off < 16; off <<= 1) {
            #pragma unroll
            for (int i = 0; i < 4; ++i)
                tm[i] = fmaxf(tm[i], __shfl_xor_sync(0xffffffffu, tm[i], off));
        }

        float p[4][4];
        #pragma unroll
        for (int i = 0; i < 4; ++i) {
            float mn    = fmaxf(mrow[i], tm[i]);
            float alpha = __expf(mrow[i] - mn);
            mrow[i] = mn;
            #pragma unroll
            for (int j = 0; j < 4; ++j) p[i][j] = __expf(s[i][j] - mn);
            lpart[i] = lpart[i] * alpha + (p[i][0] + p[i][1] + p[i][2] + p[i][3]);
            #pragma unroll
            for (int j = 0; j < 4; ++j) acc[i][j] *= alpha;
        }

        __syncthreads();  // everyone done reading Kt

        // ---- write P transposed into the Kt memory ----
        #pragma unroll
        for (int j = 0; j < 4; ++j)
            #pragma unroll
            for (int i = 0; i < 4; ++i)
                KP[c0 + j][r0 + i] = p[i][j];

        __syncthreads();

        // ---- acc += P V  (4x4 micro-tile over d = c0..c0+3) ----
        #pragma unroll 8
        for (int c = 0; c < BN; ++c) {
            float4 pa = *(const float4*)&KP[c][r0];
            float4 vb = *(const float4*)&Vs[c][c0];
            acc[0][0] += pa.x * vb.x; acc[0][1] += pa.x * vb.y; acc[0][2] += pa.x * vb.z; acc[0][3] += pa.x * vb.w;
            acc[1][0] += pa.y * vb.x; acc[1][1] += pa.y * vb.y; acc[1][2] += pa.y * vb.z; acc[1][3] += pa.y * vb.w;
            acc[2][0] += pa.z * vb.x; acc[2][1] += pa.z * vb.y; acc[2][2] += pa.z * vb.z; acc[2][3] += pa.z * vb.w;
            acc[3][0] += pa.w * vb.x; acc[3][1] += pa.w * vb.y; acc[3][2] += pa.w * vb.z; acc[3][3] += pa.w * vb.w;
        }
    }

    // ---- finalize: full row sum across the 16-lane group, divide, store ----
    #pragma unroll
    for (int off = 1; off < 16; off <<= 1) {
        #pragma unroll
        for (int i = 0; i < 4; ++i)
            lpart[i] += __shfl_xor_sync(0xffffffffu, lpart[i], off);
    }

    #pragma unroll
    for (int i = 0; i < 4; ++i) {
        float inv = 1.0f / lpart[i];
        float4 o;
        o.x = acc[i][0] * inv;
        o.y = acc[i][1] * inv;
        o.z = acc[i][2] * inv;
        o.w = acc[i][3] * inv;
        *(float4*)&g_attn[base + (size_t)(q0 + r0 + i) * DD + c0] = o;
    }
}

// ---------------------------------------------------------------------------
// Projection GEMM: out[M,N] = A[M,K] @ W[K,N] + b,  M=4096, N=K=1024.
// 64x64 block tile, BK=16, 256 threads, 4x4 micro-tile.
// ---------------------------------------------------------------------------
__global__ __launch_bounds__(256) void proj_kernel(
    const float* __restrict__ Wp,
    const float* __restrict__ bp,
    float* __restrict__ out)
{
    __shared__ float As[16][BM];   // A transposed: As[k][m]
    __shared__ float Ws[16][BN];   // Ws[k][n]

    const int tid = threadIdx.x;
    const int tr = tid >> 4;
    const int tc = tid & 15;
    const int m0 = blockIdx.y * BM;
    const int n0 = blockIdx.x * BN;

    const float* A = g_attn;

    float acc[4][4];
    #pragma unroll
    for (int i = 0; i < 4; ++i)
        #pragma unroll
        for (int j = 0; j < 4; ++j) acc[i][j] = 0.0f;

    for (int k0 = 0; k0 < DD; k0 += 16) {
        {
            const int m  = tid >> 2;
            const int kk = (tid & 3) * 4;
            float4 v = *(const float4*)(A + (size_t)(m0 + m) * DD + k0 + kk);
            As[kk + 0][m] = v.x;
            As[kk + 1][m] = v.y;
            As[kk + 2][m] = v.z;
            As[kk + 3][m] = v.w;
        }
        {
            const int k  = tid >> 4;
            const int nn = (tid & 15) * 4;
            *(float4*)&Ws[k][nn] = *(const float4*)(Wp + (size_t)(k0 + k) * DD + n0 + nn);
        }
        __syncthreads();

        #pragma unroll
        for (int k = 0; k < 16; ++k) {
            float4 a4 = *(const float4*)&As[k][tr * 4];
            float4 w4 = *(const float4*)&Ws[k][tc * 4];
            acc[0][0] += a4.x * w4.x; acc[0][1] += a4.x * w4.y; acc[0][2] += a4.x * w4.z; acc[0][3] += a4.x * w4.w;
            acc[1][0] += a4.y * w4.x; acc[1][1] += a4.y * w4.y; acc[1][2] += a4.y * w4.z; acc[1][3] += a4.y * w4.w;
            acc[2][0] += a4.z * w4.x; acc[2][1] += a4.z * w4.y; acc[2][2] += a4.z * w4.z; acc[2][3] += a4.z * w4.w;
            acc[3][0] += a4.w * w4.x; acc[3][1] += a4.w * w4.y; acc[3][2] += a4.w * w4.z; acc[3][3] += a4.w * w4.w;
        }
        __syncthreads();
    }

    float4 bb = *(const float4*)(bp + n0 + tc * 4);
    #pragma unroll
    for (int i = 0; i < 4; ++i) {
        float4 o;
        o.x = acc[i][0] + bb.x;
        o.y = acc[i][1] + bb.y;
        o.z = acc[i][2] + bb.z;
        o.w = acc[i][3] + bb.w;
        *(float4*)&out[(size_t)(m0 + tr * 4 + i) * DD + n0 + tc * 4] = o;
    }
}

extern "C" void kernel_launch(void* const* d_in, const int* in_sizes, int n_in,
                              void* d_out, int out_size)
{
    const float* Q  = (const float*)d_in[0];
    const float* K  = (const float*)d_in[1];
    const float* V  = (const float*)d_in[2];
    const float* Wp = (const float*)d_in[3];
    const float* bp = (const float*)d_in[4];
    float* out = (float*)d_out;

    dim3 gA(LL / BM, HH, BB);     // (32, 16, 2)
    attn_kernel<<<gA, 256>>>(Q, K, V);

    dim3 gP(DD / BN, (BB * LL) / BM);  // (16, 64)
    proj_kernel<<<gP, 256>>>(Wp, bp, out);
}